// round 1
// baseline (speedup 1.0000x reference)
#include <cuda_runtime.h>
#include <math.h>
#include <stdint.h>

#define BB 8
#define TT 1024
#define DM 1024
#define NH 8
#define DK 128
#define MROWS (BB*TT)   /* 8192 */

// ---------------- scratch (device globals; no cudaMalloc allowed) ----------
__device__ float g_qh[(size_t)MROWS * DM];      // 32 MB  qh_cat[row][h*128+d]
__device__ float g_kh[(size_t)MROWS * DM];      // 32 MB  kh_cat
__device__ float g_vh[(size_t)MROWS * DK];      // 4 MB   vh[row][d]
__device__ float g_oh[(size_t)NH * MROWS * DK]; // 33 MB  per-head O
__device__ float g_om[(size_t)MROWS * DK];      // 4 MB   head mean

// ---------------------------------------------------------------------------
// Generic fp32 GEMM: C[M x N] = A[M x K] * B
// B element (kk, n) is at  B + kk*ldb + (n & 127) + (n >> 7)*bstride
//   - Wq/Wk cat (H,DM,DK):  ldb=128,  bstride=DM*DK (=131072)
//   - Wv (DM,DK):           ldb=128,  bstride=0 (N=128)
//   - Wo (DK,DM):           ldb=1024, bstride=128  (== kk*1024 + n)
// BM=BN=128, BK=8, 256 threads, 8x8 per-thread microtile.
// ---------------------------------------------------------------------------
__global__ __launch_bounds__(256)
void sgemm_kernel(const float* __restrict__ A, const float* __restrict__ B,
                  float* __restrict__ C, int M, int N, int K,
                  int lda, int ldb, int bstride, int ldc)
{
    __shared__ float As[8][128];
    __shared__ float Bs[8][128];

    const int tid  = threadIdx.x;
    const int row0 = blockIdx.y * 128;
    const int col0 = blockIdx.x * 128;

    const float* Ablk = A + (size_t)row0 * lda;
    const float* Bblk = B + (size_t)(col0 >> 7) * bstride;

    const int tx = tid & 15;         // 0..15 -> 8 cols each
    const int ty = tid >> 4;         // 0..15 -> 8 rows each
    const int am = tid >> 1;         // 0..127
    const int ak = (tid & 1) * 4;    // 0 or 4
    const int bk = tid >> 5;         // 0..7
    const int bn = (tid & 31) * 4;   // 0..124

    float acc[8][8];
#pragma unroll
    for (int i = 0; i < 8; i++)
#pragma unroll
        for (int j = 0; j < 8; j++) acc[i][j] = 0.f;

    for (int k0 = 0; k0 < K; k0 += 8) {
        float4 av = *(const float4*)(Ablk + (size_t)am * lda + (k0 + ak));
        As[ak + 0][am] = av.x;
        As[ak + 1][am] = av.y;
        As[ak + 2][am] = av.z;
        As[ak + 3][am] = av.w;
        float4 bv = *(const float4*)(Bblk + (size_t)(k0 + bk) * ldb + bn);
        *(float4*)&Bs[bk][bn] = bv;
        __syncthreads();

#pragma unroll
        for (int kk = 0; kk < 8; kk++) {
            float a[8], b[8];
            *(float4*)&a[0] = *(const float4*)&As[kk][ty * 8];
            *(float4*)&a[4] = *(const float4*)&As[kk][ty * 8 + 4];
            *(float4*)&b[0] = *(const float4*)&Bs[kk][tx * 8];
            *(float4*)&b[4] = *(const float4*)&Bs[kk][tx * 8 + 4];
#pragma unroll
            for (int i = 0; i < 8; i++)
#pragma unroll
                for (int j = 0; j < 8; j++)
                    acc[i][j] += a[i] * b[j];
        }
        __syncthreads();
    }

#pragma unroll
    for (int i = 0; i < 8; i++) {
        float* crow = C + (size_t)(row0 + ty * 8 + i) * ldc + col0 + tx * 8;
        *(float4*)(crow)     = make_float4(acc[i][0], acc[i][1], acc[i][2], acc[i][3]);
        *(float4*)(crow + 4) = make_float4(acc[i][4], acc[i][5], acc[i][6], acc[i][7]);
    }
}

// ---------------------------------------------------------------------------
// Fused attention: one block = 32 query rows of one (h, b) pair.
// smem: S[32][1024] (128KB) + Qt[128][32] (16KB) + KV[128][128] (64KB) = 208KB
// Phase 1: scores (causal-limited K tiles), Phase 2: softmax + attn write,
// Phase 3: P @ V -> per-head O.
// ---------------------------------------------------------------------------
__global__ __launch_bounds__(256, 1)
void attn_kernel(const float* __restrict__ qh, const float* __restrict__ kh,
                 const float* __restrict__ vh, float* __restrict__ attn,
                 float* __restrict__ oh)
{
    extern __shared__ float sh[];
    float* Ssm = sh;                       // [32][1024]
    float* Qt  = sh + 32 * 1024;           // [128][32]  (d-major)
    float* KV  = Qt + 128 * 32;            // [128][128]

    const int tid  = threadIdx.x;
    const int qt   = blockIdx.x;
    const int t0   = qt * 32;
    const int pair = blockIdx.y;           // h*8 + b
    const int h    = pair >> 3;
    const int b    = pair & 7;
    const int n_tiles = (t0 + 32 + 127) >> 7;   // causal K-tile count

    // ---- load Q tile transposed: Qt[d][r] ----
    {
        const int r = tid & 31;
        const int dbase = (tid >> 5) * 4;
        const float* qb = qh + (size_t)(b * TT + t0 + r) * DM + h * DK;
#pragma unroll
        for (int dd = 0; dd < 4; dd++) {
            int d0 = dbase + dd * 32;
            float4 v = *(const float4*)(qb + d0);
            Qt[(d0 + 0) * 32 + r] = v.x;
            Qt[(d0 + 1) * 32 + r] = v.y;
            Qt[(d0 + 2) * 32 + r] = v.z;
            Qt[(d0 + 3) * 32 + r] = v.w;
        }
    }

    const int ty = tid >> 5;     // 0..7
    const int tx = tid & 31;     // 0..31
    const int r0 = ty * 4;
    const int c0 = tx * 4;

    // ---- Phase 1: scores ----
    const float* kbase = kh + (size_t)(b * TT) * DM + h * DK;
    for (int st = 0; st < n_tiles; st++) {
        __syncthreads();
        {   // load K tile transposed: KV[d][s]
            const int s = tid & 127;
            const int dhalf = (tid >> 7) * 4;      // 0 or 4
            const float* kb = kbase + (size_t)(st * 128 + s) * DM;
#pragma unroll
            for (int it = 0; it < 16; it++) {
                int d0 = it * 8 + dhalf;
                float4 v = *(const float4*)(kb + d0);
                KV[(d0 + 0) * 128 + s] = v.x;
                KV[(d0 + 1) * 128 + s] = v.y;
                KV[(d0 + 2) * 128 + s] = v.z;
                KV[(d0 + 3) * 128 + s] = v.w;
            }
        }
        __syncthreads();

        float acc[4][4] = {{0.f}};
#pragma unroll 4
        for (int d = 0; d < 128; d++) {
            float4 qv = *(const float4*)&Qt[d * 32 + r0];
            float4 kv = *(const float4*)&KV[d * 128 + c0];
            acc[0][0] += qv.x * kv.x; acc[0][1] += qv.x * kv.y; acc[0][2] += qv.x * kv.z; acc[0][3] += qv.x * kv.w;
            acc[1][0] += qv.y * kv.x; acc[1][1] += qv.y * kv.y; acc[1][2] += qv.y * kv.z; acc[1][3] += qv.y * kv.w;
            acc[2][0] += qv.z * kv.x; acc[2][1] += qv.z * kv.y; acc[2][2] += qv.z * kv.z; acc[2][3] += qv.z * kv.w;
            acc[3][0] += qv.w * kv.x; acc[3][1] += qv.w * kv.y; acc[3][2] += qv.w * kv.z; acc[3][3] += qv.w * kv.w;
        }
#pragma unroll
        for (int i = 0; i < 4; i++)
            *(float4*)&Ssm[(r0 + i) * 1024 + st * 128 + c0] =
                make_float4(acc[i][0], acc[i][1], acc[i][2], acc[i][3]);
    }
    __syncthreads();

    // ---- Phase 2: causal softmax + attn write ----
    {
        const int w = tid >> 5, lane = tid & 31;
        const float scale = 0.08838834764831845f;   // 1/sqrt(128)
        const int slim = n_tiles * 128;
        for (int rr = 0; rr < 4; rr++) {
            const int r = w * 4 + rr;
            const int t = t0 + r;
            float* srow = &Ssm[r * 1024];

            float m = -1e30f;
            for (int s = lane; s <= t; s += 32) m = fmaxf(m, srow[s]);
#pragma unroll
            for (int o = 16; o; o >>= 1) m = fmaxf(m, __shfl_xor_sync(~0u, m, o));

            float sum = 0.f;
            for (int s = lane; s <= t; s += 32) {
                float e = __expf((srow[s] - m) * scale);
                srow[s] = e;
                sum += e;
            }
#pragma unroll
            for (int o = 16; o; o >>= 1) sum += __shfl_xor_sync(~0u, sum, o);
            const float rinv = 1.0f / sum;

            float* arow = attn + ((size_t)pair * TT + t) * TT;
            for (int s = lane; s < TT; s += 32) {
                float p = (s <= t) ? srow[s] * rinv : 0.f;
                if (s < slim) srow[s] = p;
                arow[s] = p;
            }
        }
    }

    // ---- Phase 3: P @ V ----
    float oacc[4][4] = {{0.f}};
    const float* vbase = vh + (size_t)(b * TT) * DK;
    for (int st = 0; st < n_tiles; st++) {
        __syncthreads();
        {   // load V tile natural: KV[s][d]
            const int sfix = tid >> 5;            // 0..7
            const int d0 = (tid & 31) * 4;
#pragma unroll
            for (int it = 0; it < 16; it++) {
                int s = sfix + it * 8;
                float4 v = *(const float4*)(vbase + (size_t)(st * 128 + s) * DK + d0);
                *(float4*)&KV[s * 128 + d0] = v;
            }
        }
        __syncthreads();

#pragma unroll 4
        for (int k = 0; k < 128; k++) {
            float4 vv = *(const float4*)&KV[k * 128 + c0];
            float p0 = Ssm[(r0 + 0) * 1024 + st * 128 + k];
            float p1 = Ssm[(r0 + 1) * 1024 + st * 128 + k];
            float p2 = Ssm[(r0 + 2) * 1024 + st * 128 + k];
            float p3 = Ssm[(r0 + 3) * 1024 + st * 128 + k];
            oacc[0][0] += p0 * vv.x; oacc[0][1] += p0 * vv.y; oacc[0][2] += p0 * vv.z; oacc[0][3] += p0 * vv.w;
            oacc[1][0] += p1 * vv.x; oacc[1][1] += p1 * vv.y; oacc[1][2] += p1 * vv.z; oacc[1][3] += p1 * vv.w;
            oacc[2][0] += p2 * vv.x; oacc[2][1] += p2 * vv.y; oacc[2][2] += p2 * vv.z; oacc[2][3] += p2 * vv.w;
            oacc[3][0] += p3 * vv.x; oacc[3][1] += p3 * vv.y; oacc[3][2] += p3 * vv.z; oacc[3][3] += p3 * vv.w;
        }
    }

    float* ob = oh + ((size_t)h * MROWS + (size_t)b * TT + t0) * DK;
#pragma unroll
    for (int i = 0; i < 4; i++)
        *(float4*)&ob[(size_t)(r0 + i) * DK + c0] =
            make_float4(oacc[i][0], oacc[i][1], oacc[i][2], oacc[i][3]);
}

// ---------------------------------------------------------------------------
__global__ __launch_bounds__(256)
void reduce_mean_kernel(const float* __restrict__ oh, float* __restrict__ om)
{
    const size_t i = (size_t)blockIdx.x * 256 + threadIdx.x;   // over MROWS*DK
    float s = 0.f;
#pragma unroll
    for (int h = 0; h < NH; h++) s += oh[(size_t)h * MROWS * DK + i];
    om[i] = s * 0.125f;
}

// ---------------------------------------------------------------------------
extern "C" void kernel_launch(void* const* d_in, const int* in_sizes, int n_in,
                              void* d_out, int out_size)
{
    const float* q  = (const float*)d_in[0];
    const float* k  = (const float*)d_in[1];
    const float* v  = (const float*)d_in[2];
    /* d_in[3] = mask: exact causal tril; handled analytically */
    const float* Wq = (const float*)d_in[4];
    const float* Wk = (const float*)d_in[5];
    const float* Wv = (const float*)d_in[6];
    const float* Wo = (const float*)d_in[7];

    float* out  = (float*)d_out;                          // (B,T,DM)
    float* attn = out + (size_t)MROWS * DM;               // (H,B,T,S)

    float *qh, *kh, *vh, *oh, *om;
    cudaGetSymbolAddress((void**)&qh, g_qh);
    cudaGetSymbolAddress((void**)&kh, g_kh);
    cudaGetSymbolAddress((void**)&vh, g_vh);
    cudaGetSymbolAddress((void**)&oh, g_oh);
    cudaGetSymbolAddress((void**)&om, g_om);

    // attention kernel needs 208KB dynamic smem
    const int attn_smem = (32 * 1024 + 128 * 32 + 128 * 128) * (int)sizeof(float);
    cudaFuncSetAttribute(attn_kernel, cudaFuncAttributeMaxDynamicSharedMemorySize,
                         attn_smem);

    dim3 blk(256);

    // projections: qh_cat, kh_cat (N=1024), vh (N=128)
    sgemm_kernel<<<dim3(DM / 128, MROWS / 128), blk>>>(
        q, Wq, qh, MROWS, DM, DM, DM, DK, DM * DK, DM);
    sgemm_kernel<<<dim3(DM / 128, MROWS / 128), blk>>>(
        k, Wk, kh, MROWS, DM, DM, DM, DK, DM * DK, DM);
    sgemm_kernel<<<dim3(DK / 128, MROWS / 128), blk>>>(
        v, Wv, vh, MROWS, DK, DM, DM, DK, 0, DK);

    // fused attention
    attn_kernel<<<dim3(TT / 32, NH * BB), blk, attn_smem>>>(qh, kh, vh, attn, oh);

    // head mean
    reduce_mean_kernel<<<dim3((MROWS * DK) / 256), blk>>>(oh, om);

    // out = Omean @ Wo
    sgemm_kernel<<<dim3(DM / 128, MROWS / 128), blk>>>(
        om, Wo, out, MROWS, DM, DK, DK, DM, 128, DM);
}

// round 3
// speedup vs baseline: 2.7219x; 2.7219x over previous
#include <cuda_runtime.h>
#include <cuda_bf16.h>
#include <stdint.h>
#include <math.h>

#define BB 8
#define TT 1024
#define DM 1024
#define NH 8
#define DK 128
#define MROWS (BB*TT)   /* 8192 */

// ---------------- scratch (device globals; no cudaMalloc allowed) ----------
__device__ float g_qh [(size_t)MROWS * DM];      // 32 MB
__device__ float g_kh [(size_t)MROWS * DM];      // 32 MB
__device__ float g_vh [(size_t)MROWS * DK];      // 4 MB
__device__ float g_vhT[(size_t)MROWS * DK];      // 4 MB  [b][128][1024]
__device__ float g_oh [(size_t)NH * MROWS * DK]; // 33 MB per-head O
__device__ float g_om [(size_t)MROWS * DK];      // 4 MB
__device__ float g_wqT[(size_t)NH * DM * DK];    // 4 MB  [h][128][1024]
__device__ float g_wkT[(size_t)NH * DM * DK];    // 4 MB
__device__ float g_wvT[(size_t)DM * DK];         // 0.5 MB [128][1024]
__device__ float g_woT[(size_t)DM * DK];         // 0.5 MB [1024][128]

// ======================= helpers ==============================
__device__ __forceinline__ uint32_t smem_u32(const void* p) {
    uint32_t a;
    asm("{ .reg .u64 t; cvta.to.shared.u64 t, %1; cvt.u32.u64 %0, t; }"
        : "=r"(a) : "l"(p));
    return a;
}

__device__ __forceinline__ uint32_t sw128(uint32_t off) {
    return off ^ ((off >> 3) & 0x70);
}

__device__ __forceinline__ void ldm4(uint32_t* d, uint32_t addr) {
    asm volatile("ldmatrix.sync.aligned.m8n8.x4.shared.b16 {%0,%1,%2,%3}, [%4];"
                 : "=r"(d[0]), "=r"(d[1]), "=r"(d[2]), "=r"(d[3]) : "r"(addr));
}

__device__ __forceinline__ void mma16816(float* c, const uint32_t* a, const uint32_t* b) {
    asm volatile(
        "mma.sync.aligned.m16n8k16.row.col.f32.bf16.bf16.f32 "
        "{%0,%1,%2,%3}, {%4,%5,%6,%7}, {%8,%9}, {%0,%1,%2,%3};"
        : "+f"(c[0]), "+f"(c[1]), "+f"(c[2]), "+f"(c[3])
        : "r"(a[0]), "r"(a[1]), "r"(a[2]), "r"(a[3]), "r"(b[0]), "r"(b[1]));
}

__device__ __forceinline__ void split2(float x, float y, uint32_t& hi, uint32_t& lo) {
    __nv_bfloat162 h = __floats2bfloat162_rn(x, y);
    float rx = x - __bfloat162float(h.x);
    float ry = y - __bfloat162float(h.y);
    __nv_bfloat162 l = __floats2bfloat162_rn(rx, ry);
    hi = *reinterpret_cast<uint32_t*>(&h);
    lo = *reinterpret_cast<uint32_t*>(&l);
}

// ============================================================================
// Generic split-bf16 HMMA GEMM:  D[128x128 tile] = A(MxK) * B(NxK)^T
// fp32 gmem operands -> bf16 hi/lo SW128 smem tiles -> ldmatrix + mma.sync.
// Batched over blockIdx.z = z1*8 + z2 with per-operand (S1,S2) strides.
// mode: 0 = plain, 1 = causal score tile skip, 2 = causal K-limit (PV).
// smem: 2 bufs x [A_hi|A_lo|B_hi|B_lo] x 16KB = 128 KB.
// ============================================================================
__global__ __launch_bounds__(256)
void gemm_bf16s(const float* __restrict__ A, const float* __restrict__ B,
                float* __restrict__ C, int K, int lda, int ldb, int ldc,
                long long aS1, long long aS2, long long bS1, long long bS2,
                long long cS1, long long cS2, int mode)
{
    extern __shared__ char sm[];
    const int tid  = threadIdx.x;
    const int wid  = tid >> 5;
    const int lane = tid & 31;
    const int row0 = blockIdx.y * 128;
    const int col0 = blockIdx.x * 128;
    if (mode == 1 && col0 >= row0 + 128) return;     // fully above diagonal

    const int z1 = blockIdx.z >> 3, z2 = blockIdx.z & 7;
    const float* Ab = A + (size_t)z1 * aS1 + (size_t)z2 * aS2;
    const float* Bb = B + (size_t)z1 * bS1 + (size_t)z2 * bS2;
    float*       Cb = C + (size_t)z1 * cS1 + (size_t)z2 * cS2;

    const int Keff = (mode == 2) ? (row0 + 128 < K ? row0 + 128 : K) : K;
    const int nCh  = Keff >> 6;                      // 64-wide K chunks

    const uint32_t sbase = smem_u32(sm);

    // ---- fill addressing (all 256 threads) ----
    const int lrow = tid >> 1;                       // 0..127
    const int lk   = (tid & 1) * 32;                 // 0 or 32
    const float* arow = Ab + (size_t)(row0 + lrow) * lda + lk;
    const float* brow = Bb + (size_t)(col0 + lrow) * ldb + lk;
    const uint32_t rb = (uint32_t)lrow * 128 + (uint32_t)lk * 2;

    // ---- warp tiling: 2 (m) x 4 (n) warps; each 64 rows x 32 cols ----
    const int wm = (wid >> 2) * 64;
    const int wn = (wid & 3) * 32;

    // ldmatrix per-thread base byte offsets within a 16KB tile
    uint32_t aBase[4], bBase[2];
#pragma unroll
    for (int mt = 0; mt < 4; mt++) {
        int r = wm + mt * 16 + ((lane >> 3) & 1) * 8 + (lane & 7);
        aBase[mt] = (uint32_t)r * 128 + (uint32_t)((lane >> 4) * 8) * 2;
    }
#pragma unroll
    for (int np = 0; np < 2; np++) {
        int r = wn + np * 16 + (lane >> 4) * 8 + (lane & 7);
        bBase[np] = (uint32_t)r * 128 + (uint32_t)(((lane >> 3) & 1) * 8) * 2;
    }

    float acc[4][4][4];
#pragma unroll
    for (int mt = 0; mt < 4; mt++)
#pragma unroll
        for (int nt = 0; nt < 4; nt++)
#pragma unroll
            for (int i = 0; i < 4; i++) acc[mt][nt][i] = 0.f;

    // ---- fill lambda-ish macro ----
#define FILL_CHUNK(cc) do {                                                   \
        char* tb = sm + ((cc) & 1) * 65536;                                   \
        const int k0 = (cc) << 6;                                             \
        _Pragma("unroll")                                                     \
        for (int i = 0; i < 8; i++) {                                         \
            float4 va = *(const float4*)(arow + k0 + i * 4);                  \
            uint2 hiu, lou;                                                   \
            split2(va.x, va.y, hiu.x, lou.x);                                 \
            split2(va.z, va.w, hiu.y, lou.y);                                 \
            uint32_t sw = sw128(rb + i * 8);                                  \
            *(uint2*)(tb + sw)         = hiu;                                 \
            *(uint2*)(tb + 16384 + sw) = lou;                                 \
            float4 vb = *(const float4*)(brow + k0 + i * 4);                  \
            split2(vb.x, vb.y, hiu.x, lou.x);                                 \
            split2(vb.z, vb.w, hiu.y, lou.y);                                 \
            *(uint2*)(tb + 32768 + sw) = hiu;                                 \
            *(uint2*)(tb + 49152 + sw) = lou;                                 \
        }                                                                     \
    } while (0)

    FILL_CHUNK(0);
    __syncthreads();

    for (int c = 0; c < nCh; ++c) {
        if (c + 1 < nCh) FILL_CHUNK(c + 1);

        const uint32_t tb = sbase + (c & 1) * 65536;
#pragma unroll
        for (int ks = 0; ks < 4; ks++) {
            const uint32_t kb = (uint32_t)ks * 32;
            uint32_t ah[4][4], al[4][4], bh[2][4], bl[2][4];
#pragma unroll
            for (int mt = 0; mt < 4; mt++)
                ldm4(ah[mt], tb + sw128(aBase[mt] + kb));
#pragma unroll
            for (int np = 0; np < 2; np++)
                ldm4(bh[np], tb + 32768 + sw128(bBase[np] + kb));
#pragma unroll
            for (int mt = 0; mt < 4; mt++)
#pragma unroll
                for (int nt = 0; nt < 4; nt++)
                    mma16816(acc[mt][nt], ah[mt], &bh[nt >> 1][(nt & 1) * 2]);
#pragma unroll
            for (int np = 0; np < 2; np++)
                ldm4(bl[np], tb + 49152 + sw128(bBase[np] + kb));
#pragma unroll
            for (int mt = 0; mt < 4; mt++)
#pragma unroll
                for (int nt = 0; nt < 4; nt++)
                    mma16816(acc[mt][nt], ah[mt], &bl[nt >> 1][(nt & 1) * 2]);
#pragma unroll
            for (int mt = 0; mt < 4; mt++)
                ldm4(al[mt], tb + 16384 + sw128(aBase[mt] + kb));
#pragma unroll
            for (int mt = 0; mt < 4; mt++)
#pragma unroll
                for (int nt = 0; nt < 4; nt++)
                    mma16816(acc[mt][nt], al[mt], &bh[nt >> 1][(nt & 1) * 2]);
        }
        __syncthreads();
    }

    // ---- epilogue: write fp32 accumulators ----
#pragma unroll
    for (int mt = 0; mt < 4; mt++) {
        const int r = row0 + wm + mt * 16 + (lane >> 2);
#pragma unroll
        for (int nt = 0; nt < 4; nt++) {
            const int cc = col0 + wn + nt * 8 + (lane & 3) * 2;
            float* p = Cb + (size_t)r * ldc + cc;
            *(float2*)p = make_float2(acc[mt][nt][0], acc[mt][nt][1]);
            *(float2*)(p + (size_t)8 * ldc) = make_float2(acc[mt][nt][2], acc[mt][nt][3]);
        }
    }
#undef FILL_CHUNK
}

// ============================================================================
// Batched transpose: in (z, R, C) -> out (z, C, R).  block (32,8)
// ============================================================================
__global__ __launch_bounds__(256)
void transpose_kernel(const float* __restrict__ in, float* __restrict__ out,
                      int R, int C)
{
    __shared__ float t[32][33];
    const float* ib = in  + (size_t)blockIdx.z * R * C;
    float*       ob = out + (size_t)blockIdx.z * R * C;
    const int r0 = blockIdx.y * 32, c0 = blockIdx.x * 32;
    const int tx = threadIdx.x, ty = threadIdx.y;
#pragma unroll
    for (int i = 0; i < 32; i += 8)
        t[ty + i][tx] = ib[(size_t)(r0 + ty + i) * C + c0 + tx];
    __syncthreads();
#pragma unroll
    for (int i = 0; i < 32; i += 8)
        ob[(size_t)(c0 + ty + i) * R + r0 + tx] = t[tx][ty + i];
}

// ============================================================================
// In-place causal softmax over attn rows. One warp per row (gw = pair*1024+t).
// Keeps s<=t of softmax(score/temper), zeros s>t. Single read+write pass.
// ============================================================================
__global__ __launch_bounds__(256)
void softmax_kernel(float* __restrict__ attn)
{
    const int gw   = blockIdx.x * 8 + (threadIdx.x >> 5);
    const int lane = threadIdx.x & 31;
    const int t    = gw & (TT - 1);
    float* row = attn + (size_t)gw * TT;

    float v[32];
    float m = -1e30f;
#pragma unroll
    for (int i = 0; i < 32; i++) {
        const int s = i * 32 + lane;
        v[i] = (s <= t) ? row[s] : -1e30f;
        m = fmaxf(m, v[i]);
    }
#pragma unroll
    for (int o = 16; o; o >>= 1) m = fmaxf(m, __shfl_xor_sync(~0u, m, o));

    const float scale = 0.08838834764831845f;   // 1/sqrt(128)
    float sum = 0.f;
#pragma unroll
    for (int i = 0; i < 32; i++) {
        const int s = i * 32 + lane;
        float e = (s <= t) ? __expf((v[i] - m) * scale) : 0.f;
        v[i] = e;
        sum += e;
    }
#pragma unroll
    for (int o = 16; o; o >>= 1) sum += __shfl_xor_sync(~0u, sum, o);
    const float rinv = 1.0f / sum;

#pragma unroll
    for (int i = 0; i < 32; i++) {
        const int s = i * 32 + lane;
        row[s] = v[i] * rinv;
    }
}

// ============================================================================
__global__ __launch_bounds__(256)
void reduce_mean_kernel(const float* __restrict__ oh, float* __restrict__ om)
{
    const size_t i = (size_t)blockIdx.x * 256 + threadIdx.x;
    float s = 0.f;
#pragma unroll
    for (int h = 0; h < NH; h++) s += oh[(size_t)h * MROWS * DK + i];
    om[i] = s * 0.125f;
}

// ============================================================================
extern "C" void kernel_launch(void* const* d_in, const int* in_sizes, int n_in,
                              void* d_out, int out_size)
{
    const float* q  = (const float*)d_in[0];
    const float* k  = (const float*)d_in[1];
    const float* v  = (const float*)d_in[2];
    /* d_in[3] = mask: exact causal tril; handled analytically */
    const float* Wq = (const float*)d_in[4];
    const float* Wk = (const float*)d_in[5];
    const float* Wv = (const float*)d_in[6];
    const float* Wo = (const float*)d_in[7];

    float* out  = (float*)d_out;                       // (B,T,DM)
    float* attn = out + (size_t)MROWS * DM;            // (H,B,T,S)

    float *qh, *kh, *vh, *vhT, *oh, *om, *wqT, *wkT, *wvT, *woT;
    cudaGetSymbolAddress((void**)&qh,  g_qh);
    cudaGetSymbolAddress((void**)&kh,  g_kh);
    cudaGetSymbolAddress((void**)&vh,  g_vh);
    cudaGetSymbolAddress((void**)&vhT, g_vhT);
    cudaGetSymbolAddress((void**)&oh,  g_oh);
    cudaGetSymbolAddress((void**)&om,  g_om);
    cudaGetSymbolAddress((void**)&wqT, g_wqT);
    cudaGetSymbolAddress((void**)&wkT, g_wkT);
    cudaGetSymbolAddress((void**)&wvT, g_wvT);
    cudaGetSymbolAddress((void**)&woT, g_woT);

    const int GSM = 2 * 4 * 16384;                     // 128 KB dynamic smem
    cudaFuncSetAttribute(gemm_bf16s, cudaFuncAttributeMaxDynamicSharedMemorySize, GSM);

    dim3 tb(32, 8);

    // ---- weight transposes (K-major B operands) ----
    transpose_kernel<<<dim3(4, 32, 8), tb>>>(Wq, wqT, 1024, 128);   // (8,128,1024)
    transpose_kernel<<<dim3(4, 32, 8), tb>>>(Wk, wkT, 1024, 128);
    transpose_kernel<<<dim3(4, 32, 1), tb>>>(Wv, wvT, 1024, 128);   // (128,1024)
    transpose_kernel<<<dim3(32, 4, 1), tb>>>(Wo, woT, 128, 1024);   // (1024,128)

    // ---- projections ----
    gemm_bf16s<<<dim3(8, 64, 1), 256, GSM>>>(q, wqT, qh, 1024, 1024, 1024, 1024,
                                             0,0, 0,0, 0,0, 0);
    gemm_bf16s<<<dim3(8, 64, 1), 256, GSM>>>(k, wkT, kh, 1024, 1024, 1024, 1024,
                                             0,0, 0,0, 0,0, 0);
    gemm_bf16s<<<dim3(1, 64, 1), 256, GSM>>>(v, wvT, vh, 1024, 1024, 1024, 128,
                                             0,0, 0,0, 0,0, 0);
    transpose_kernel<<<dim3(4, 32, 8), tb>>>(vh, vhT, 1024, 128);   // per-b (128,1024)

    // ---- scores = qh @ kh^T  (batched z = b*8+h, causal tile skip) ----
    gemm_bf16s<<<dim3(8, 8, 64), 256, GSM>>>(qh, kh, attn, 128, 1024, 1024, 1024,
                                             1048576LL, 128LL,      // A: b, h
                                             1048576LL, 128LL,      // B: b, h
                                             1048576LL, 8388608LL,  // C: b, h
                                             1);

    // ---- softmax in place (writes zeros above diagonal) ----
    softmax_kernel<<<dim3(NH * BB * TT / 8), 256>>>(attn);

    // ---- O_h = P @ V  (batched, causal K limit) ----
    gemm_bf16s<<<dim3(1, 8, 64), 256, GSM>>>(attn, vhT, oh, 1024, 1024, 1024, 128,
                                             1048576LL, 8388608LL,  // A: b, h
                                             131072LL,  0LL,        // B: b
                                             131072LL,  1048576LL,  // C: b, h
                                             2);

    // ---- head mean ----
    reduce_mean_kernel<<<dim3((MROWS * DK) / 256), 256>>>(oh, om);

    // ---- out = Om @ Wo ----
    gemm_bf16s<<<dim3(8, 64, 1), 256, GSM>>>(om, woT, out, 128, 128, 128, 1024,
                                             0,0, 0,0, 0,0, 0);
}

// round 4
// speedup vs baseline: 6.1375x; 2.2548x over previous
#include <cuda_runtime.h>
#include <cuda_fp16.h>
#include <stdint.h>
#include <math.h>

#define BB 8
#define TT 1024
#define DM 1024
#define NH 8
#define DK 128
#define MROWS (BB*TT)   /* 8192 */

// ---------------- scratch (device globals; no cudaMalloc allowed) ----------
__device__ __half g_q2 [(size_t)MROWS * DM];      // 16 MB  q  (A: hi only)
__device__ __half g_k2 [(size_t)MROWS * DM];      // 16 MB
__device__ __half g_v2 [(size_t)MROWS * DM];      // 16 MB
__device__ __half g_wqh[(size_t)NH * DM * DK];    // 2 MB  [h][128][1024] hi
__device__ __half g_wql[(size_t)NH * DM * DK];    // 2 MB  lo
__device__ __half g_wkh[(size_t)NH * DM * DK];
__device__ __half g_wkl[(size_t)NH * DM * DK];
__device__ __half g_wvh[(size_t)DM * DK];         // [128][1024]
__device__ __half g_wvl[(size_t)DM * DK];
__device__ __half g_woh[(size_t)DM * DK];         // [1024][128]
__device__ __half g_wol[(size_t)DM * DK];
__device__ __half g_qh [(size_t)MROWS * DM];      // 16 MB  qh hi (A of scores)
__device__ __half g_khh[(size_t)MROWS * DM];      // 16 MB  kh hi (B of scores)
__device__ __half g_khl[(size_t)MROWS * DM];      // 16 MB  kh lo
__device__ float  g_vh [(size_t)MROWS * DK];      // 4 MB   vh fp32
__device__ __half g_vth[(size_t)MROWS * DK];      // 2 MB   vhT hi [b][128][1024]
__device__ __half g_vtl[(size_t)MROWS * DK];      // 2 MB   vhT lo
__device__ __half g_ph [(size_t)NH * BB * TT * TT]; // 134 MB  P hi (A of PV)
__device__ float  g_oh [(size_t)NH * MROWS * DK]; // 33 MB per-head O
__device__ __half g_om [(size_t)MROWS * DK];      // 2 MB   head-mean hi

// ======================= helpers ==============================
__device__ __forceinline__ uint32_t smem_u32(const void* p) {
    uint32_t a;
    asm("{ .reg .u64 t; cvta.to.shared.u64 t, %1; cvt.u32.u64 %0, t; }"
        : "=r"(a) : "l"(p));
    return a;
}
__device__ __forceinline__ uint32_t sw128(uint32_t off) {
    return off ^ ((off >> 3) & 0x70);
}
__device__ __forceinline__ void ldm4(uint32_t* d, uint32_t addr) {
    asm volatile("ldmatrix.sync.aligned.m8n8.x4.shared.b16 {%0,%1,%2,%3}, [%4];"
                 : "=r"(d[0]), "=r"(d[1]), "=r"(d[2]), "=r"(d[3]) : "r"(addr));
}
__device__ __forceinline__ void mma16816(float* c, const uint32_t* a, const uint32_t* b) {
    asm volatile(
        "mma.sync.aligned.m16n8k16.row.col.f32.f16.f16.f32 "
        "{%0,%1,%2,%3}, {%4,%5,%6,%7}, {%8,%9}, {%0,%1,%2,%3};"
        : "+f"(c[0]), "+f"(c[1]), "+f"(c[2]), "+f"(c[3])
        : "r"(a[0]), "r"(a[1]), "r"(a[2]), "r"(a[3]), "r"(b[0]), "r"(b[1]));
}
#define CP16(sa, ga) \
    asm volatile("cp.async.ca.shared.global [%0], [%1], 16;" :: "r"(sa), "l"(ga))
#define CP_COMMIT() asm volatile("cp.async.commit_group;" ::: "memory")
#define CP_WAIT2()  asm volatile("cp.async.wait_group 2;"  ::: "memory")

// ============================================================================
// fp16 2-term HMMA GEMM:  D[128x128 tile] = A_hi(MxK) * (B_hi + B_lo)(NxK)^T
// All operands pre-converted fp16 row-major K-contiguous in gmem.
// 4-stage cp.async pipeline; stage = 3 tiles x 16KB (Ah, Bh, Bl) = 48KB.
// Batched over blockIdx.z = z1*8 + z2 with per-operand (S1,S2) strides.
// mode: 0 = plain, 1 = causal score tile skip, 2 = causal K-limit (PV).
// Output: fp32 C (if non-null) and/or fp16 Ch (+optional Cl split).
// ============================================================================
__global__ __launch_bounds__(256)
void gemm_h(const __half* __restrict__ Ah, const __half* __restrict__ Bh,
            const __half* __restrict__ Bl,
            float* __restrict__ C, __half* __restrict__ Ch, __half* __restrict__ Cl,
            int K, int lda, int ldb, int ldc,
            long long aS1, long long aS2, long long bS1, long long bS2,
            long long cS1, long long cS2, int mode)
{
    extern __shared__ char sm[];
    const int tid  = threadIdx.x;
    const int wid  = tid >> 5;
    const int lane = tid & 31;
    const int row0 = blockIdx.y * 128;
    const int col0 = blockIdx.x * 128;
    if (mode == 1 && col0 >= row0 + 128) return;     // fully above diagonal

    const int z1 = blockIdx.z >> 3, z2 = blockIdx.z & 7;
    const __half* Ab  = Ah + (size_t)z1 * aS1 + (size_t)z2 * aS2;
    const __half* Bhb = Bh + (size_t)z1 * bS1 + (size_t)z2 * bS2;
    const __half* Blb = Bl + (size_t)z1 * bS1 + (size_t)z2 * bS2;

    const int Keff = (mode == 2) ? (row0 + 128 < K ? row0 + 128 : K) : K;
    const int nCh  = Keff >> 6;                      // 64-wide K chunks

    const uint32_t sb = smem_u32(sm);

#define FILL(cc) do {                                                         \
        uint32_t stb = sb + ((cc) & 3) * 49152;                               \
        const int k0 = (cc) << 6;                                             \
        _Pragma("unroll")                                                     \
        for (int i = 0; i < 4; i++) {                                         \
            int id = tid + 256 * i;                                           \
            int rr = id >> 3, sg = id & 7;                                    \
            uint32_t sw = sw128((uint32_t)rr * 128 + sg * 16);                \
            CP16(stb + sw,         Ab  + (size_t)(row0 + rr) * lda + k0 + sg * 8); \
            CP16(stb + 16384 + sw, Bhb + (size_t)(col0 + rr) * ldb + k0 + sg * 8); \
            CP16(stb + 32768 + sw, Blb + (size_t)(col0 + rr) * ldb + k0 + sg * 8); \
        }                                                                     \
    } while (0)

    // ---- warp tiling: 2 (m) x 4 (n) warps; each 64 rows x 32 cols ----
    const int wm = (wid >> 2) * 64;
    const int wn = (wid & 3) * 32;

    uint32_t aBase[4], bBase[2];
#pragma unroll
    for (int mt = 0; mt < 4; mt++) {
        int r = wm + mt * 16 + ((lane >> 3) & 1) * 8 + (lane & 7);
        aBase[mt] = (uint32_t)r * 128 + (uint32_t)((lane >> 4) * 8) * 2;
    }
#pragma unroll
    for (int np = 0; np < 2; np++) {
        int r = wn + np * 16 + (lane >> 4) * 8 + (lane & 7);
        bBase[np] = (uint32_t)r * 128 + (uint32_t)(((lane >> 3) & 1) * 8) * 2;
    }

    float acc[4][4][4];
#pragma unroll
    for (int mt = 0; mt < 4; mt++)
#pragma unroll
        for (int nt = 0; nt < 4; nt++)
#pragma unroll
            for (int i = 0; i < 4; i++) acc[mt][nt][i] = 0.f;

    // ---- prologue: 3 stages in flight ----
#pragma unroll
    for (int p = 0; p < 3; p++) { if (p < nCh) FILL(p); CP_COMMIT(); }

    for (int c = 0; c < nCh; ++c) {
        CP_WAIT2();
        __syncthreads();
        const uint32_t tb = sb + (c & 3) * 49152;
#pragma unroll
        for (int ks = 0; ks < 4; ks++) {
            const uint32_t kb = (uint32_t)ks * 32;
            uint32_t a[4][4], bh2[2][4], bl2[2][4];
#pragma unroll
            for (int mt = 0; mt < 4; mt++)
                ldm4(a[mt], tb + sw128(aBase[mt] + kb));
#pragma unroll
            for (int np = 0; np < 2; np++)
                ldm4(bh2[np], tb + 16384 + sw128(bBase[np] + kb));
#pragma unroll
            for (int mt = 0; mt < 4; mt++)
#pragma unroll
                for (int nt = 0; nt < 4; nt++)
                    mma16816(acc[mt][nt], a[mt], &bh2[nt >> 1][(nt & 1) * 2]);
#pragma unroll
            for (int np = 0; np < 2; np++)
                ldm4(bl2[np], tb + 32768 + sw128(bBase[np] + kb));
#pragma unroll
            for (int mt = 0; mt < 4; mt++)
#pragma unroll
                for (int nt = 0; nt < 4; nt++)
                    mma16816(acc[mt][nt], a[mt], &bl2[nt >> 1][(nt & 1) * 2]);
        }
        int f = c + 3;
        if (f < nCh) FILL(f);
        CP_COMMIT();
    }
#undef FILL

    // ---- epilogue ----
    float*  Cb  = C  ? C  + (size_t)z1 * cS1 + (size_t)z2 * cS2 : nullptr;
    __half* Chb = Ch ? Ch + (size_t)z1 * cS1 + (size_t)z2 * cS2 : nullptr;
    __half* Clb = Cl ? Cl + (size_t)z1 * cS1 + (size_t)z2 * cS2 : nullptr;

#pragma unroll
    for (int mt = 0; mt < 4; mt++) {
        const int r = row0 + wm + mt * 16 + (lane >> 2);
#pragma unroll
        for (int nt = 0; nt < 4; nt++) {
            const int cc = col0 + wn + nt * 8 + (lane & 3) * 2;
            if (Cb) {
                float* p = Cb + (size_t)r * ldc + cc;
                *(float2*)p = make_float2(acc[mt][nt][0], acc[mt][nt][1]);
                *(float2*)(p + (size_t)8 * ldc) = make_float2(acc[mt][nt][2], acc[mt][nt][3]);
            }
            if (Chb) {
                __half2 h0 = __floats2half2_rn(acc[mt][nt][0], acc[mt][nt][1]);
                __half2 h1 = __floats2half2_rn(acc[mt][nt][2], acc[mt][nt][3]);
                *(__half2*)(Chb + (size_t)r * ldc + cc) = h0;
                *(__half2*)(Chb + (size_t)(r + 8) * ldc + cc) = h1;
                if (Clb) {
                    __half2 l0 = __floats2half2_rn(acc[mt][nt][0] - __low2float(h0),
                                                   acc[mt][nt][1] - __high2float(h0));
                    __half2 l1 = __floats2half2_rn(acc[mt][nt][2] - __low2float(h1),
                                                   acc[mt][nt][3] - __high2float(h1));
                    *(__half2*)(Clb + (size_t)r * ldc + cc) = l0;
                    *(__half2*)(Clb + (size_t)(r + 8) * ldc + cc) = l1;
                }
            }
        }
    }
}

// ============================================================================
// fp32 -> fp16 (hi only) convert, 4 elems/thread
// ============================================================================
__global__ __launch_bounds__(256)
void conv_h(const float* __restrict__ in, __half* __restrict__ out)
{
    const size_t i = ((size_t)blockIdx.x * 256 + threadIdx.x) * 4;
    float4 v = *(const float4*)(in + i);
    __half2 a = __floats2half2_rn(v.x, v.y);
    __half2 b = __floats2half2_rn(v.z, v.w);
    *(__half2*)(out + i)     = a;
    *(__half2*)(out + i + 2) = b;
}

// ============================================================================
// Batched transpose + split: fp32 in (z,R,C) -> fp16 hi/lo out (z,C,R)
// ============================================================================
__global__ __launch_bounds__(256)
void transpose_split(const float* __restrict__ in, __half* __restrict__ oh,
                     __half* __restrict__ ol, int R, int C)
{
    __shared__ float t[32][33];
    const float* ib = in + (size_t)blockIdx.z * R * C;
    __half* ohb = oh + (size_t)blockIdx.z * R * C;
    __half* olb = ol + (size_t)blockIdx.z * R * C;
    const int r0 = blockIdx.y * 32, c0 = blockIdx.x * 32;
    const int tx = threadIdx.x, ty = threadIdx.y;
#pragma unroll
    for (int i = 0; i < 32; i += 8)
        t[ty + i][tx] = ib[(size_t)(r0 + ty + i) * C + c0 + tx];
    __syncthreads();
#pragma unroll
    for (int i = 0; i < 32; i += 8) {
        float x = t[tx][ty + i];
        __half h = __float2half_rn(x);
        __half l = __float2half_rn(x - __half2float(h));
        size_t idx = (size_t)(c0 + ty + i) * R + r0 + tx;
        ohb[idx] = h;
        olb[idx] = l;
    }
}

// ============================================================================
// In-place causal softmax; also emits fp16 P_hi copy. One warp per row.
// ============================================================================
__global__ __launch_bounds__(256)
void softmax_kernel(float* __restrict__ attn, __half* __restrict__ ph)
{
    const int gw   = blockIdx.x * 8 + (threadIdx.x >> 5);
    const int lane = threadIdx.x & 31;
    const int t    = gw & (TT - 1);
    float*  row  = attn + (size_t)gw * TT;
    __half* prow = ph   + (size_t)gw * TT;

    float v[32];
    float m = -1e30f;
#pragma unroll
    for (int i = 0; i < 32; i++) {
        const int s = i * 32 + lane;
        v[i] = (s <= t) ? row[s] : -1e30f;
        m = fmaxf(m, v[i]);
    }
#pragma unroll
    for (int o = 16; o; o >>= 1) m = fmaxf(m, __shfl_xor_sync(~0u, m, o));

    const float scale = 0.08838834764831845f;   // 1/sqrt(128)
    float sum = 0.f;
#pragma unroll
    for (int i = 0; i < 32; i++) {
        const int s = i * 32 + lane;
        float e = (s <= t) ? __expf((v[i] - m) * scale) : 0.f;
        v[i] = e;
        sum += e;
    }
#pragma unroll
    for (int o = 16; o; o >>= 1) sum += __shfl_xor_sync(~0u, sum, o);
    const float rinv = 1.0f / sum;

#pragma unroll
    for (int i = 0; i < 32; i++) {
        const int s = i * 32 + lane;
        float p = v[i] * rinv;
        row[s]  = p;
        prow[s] = __float2half_rn(p);
    }
}

// ============================================================================
__global__ __launch_bounds__(256)
void reduce_mean_kernel(const float* __restrict__ oh, __half* __restrict__ om)
{
    const size_t i = (size_t)blockIdx.x * 256 + threadIdx.x;
    float s = 0.f;
#pragma unroll
    for (int h = 0; h < NH; h++) s += oh[(size_t)h * MROWS * DK + i];
    om[i] = __float2half_rn(s * 0.125f);
}

// ============================================================================
extern "C" void kernel_launch(void* const* d_in, const int* in_sizes, int n_in,
                              void* d_out, int out_size)
{
    const float* q  = (const float*)d_in[0];
    const float* k  = (const float*)d_in[1];
    const float* v  = (const float*)d_in[2];
    /* d_in[3] = mask: exact causal tril; handled analytically */
    const float* Wq = (const float*)d_in[4];
    const float* Wk = (const float*)d_in[5];
    const float* Wv = (const float*)d_in[6];
    const float* Wo = (const float*)d_in[7];

    float* out  = (float*)d_out;                       // (B,T,DM)
    float* attn = out + (size_t)MROWS * DM;            // (H,B,T,S)

    __half *q2,*k2,*v2,*wqh,*wql,*wkh,*wkl,*wvh,*wvl,*woh,*wol;
    __half *qh,*khh,*khl,*vth,*vtl,*ph,*om;
    float *vh,*oh;
    cudaGetSymbolAddress((void**)&q2,  g_q2);
    cudaGetSymbolAddress((void**)&k2,  g_k2);
    cudaGetSymbolAddress((void**)&v2,  g_v2);
    cudaGetSymbolAddress((void**)&wqh, g_wqh);
    cudaGetSymbolAddress((void**)&wql, g_wql);
    cudaGetSymbolAddress((void**)&wkh, g_wkh);
    cudaGetSymbolAddress((void**)&wkl, g_wkl);
    cudaGetSymbolAddress((void**)&wvh, g_wvh);
    cudaGetSymbolAddress((void**)&wvl, g_wvl);
    cudaGetSymbolAddress((void**)&woh, g_woh);
    cudaGetSymbolAddress((void**)&wol, g_wol);
    cudaGetSymbolAddress((void**)&qh,  g_qh);
    cudaGetSymbolAddress((void**)&khh, g_khh);
    cudaGetSymbolAddress((void**)&khl, g_khl);
    cudaGetSymbolAddress((void**)&vh,  g_vh);
    cudaGetSymbolAddress((void**)&vth, g_vth);
    cudaGetSymbolAddress((void**)&vtl, g_vtl);
    cudaGetSymbolAddress((void**)&ph,  g_ph);
    cudaGetSymbolAddress((void**)&oh,  g_oh);
    cudaGetSymbolAddress((void**)&om,  g_om);

    const int GSM = 4 * 3 * 16384;                     // 192 KB dynamic smem
    cudaFuncSetAttribute(gemm_h, cudaFuncAttributeMaxDynamicSharedMemorySize, GSM);

    dim3 tb(32, 8);

    // ---- operand preparation ----
    conv_h<<<dim3(MROWS * DM / 1024), 256>>>(q, q2);
    conv_h<<<dim3(MROWS * DM / 1024), 256>>>(k, k2);
    conv_h<<<dim3(MROWS * DM / 1024), 256>>>(v, v2);
    transpose_split<<<dim3(4, 32, 8), tb>>>(Wq, wqh, wql, 1024, 128);  // (8,128,1024)
    transpose_split<<<dim3(4, 32, 8), tb>>>(Wk, wkh, wkl, 1024, 128);
    transpose_split<<<dim3(4, 32, 1), tb>>>(Wv, wvh, wvl, 1024, 128);  // (128,1024)
    transpose_split<<<dim3(32, 4, 1), tb>>>(Wo, woh, wol, 128, 1024);  // (1024,128)

    // ---- projections ----
    gemm_h<<<dim3(8, 64, 1), 256, GSM>>>(q2, wqh, wql, nullptr, qh, nullptr,
                                         1024, 1024, 1024, 1024,
                                         0,0, 0,0, 0,0, 0);
    gemm_h<<<dim3(8, 64, 1), 256, GSM>>>(k2, wkh, wkl, nullptr, khh, khl,
                                         1024, 1024, 1024, 1024,
                                         0,0, 0,0, 0,0, 0);
    gemm_h<<<dim3(1, 64, 1), 256, GSM>>>(v2, wvh, wvl, vh, nullptr, nullptr,
                                         1024, 1024, 1024, 128,
                                         0,0, 0,0, 0,0, 0);
    transpose_split<<<dim3(4, 32, 8), tb>>>(vh, vth, vtl, 1024, 128);  // per-b (128,1024)

    // ---- scores = qh @ kh^T  (batched z = b*8+h, causal tile skip) ----
    gemm_h<<<dim3(8, 8, 64), 256, GSM>>>(qh, khh, khl, attn, nullptr, nullptr,
                                         128, 1024, 1024, 1024,
                                         1048576LL, 128LL,      // A: b, h
                                         1048576LL, 128LL,      // B: b, h
                                         1048576LL, 8388608LL,  // C: b, h
                                         1);

    // ---- softmax in place; emits P_hi ----
    softmax_kernel<<<dim3(NH * BB * TT / 8), 256>>>(attn, ph);

    // ---- O_h = P @ V  (batched, causal K limit) ----
    gemm_h<<<dim3(1, 8, 64), 256, GSM>>>(ph, vth, vtl, oh, nullptr, nullptr,
                                         1024, 1024, 1024, 128,
                                         1048576LL, 8388608LL,  // A: b, h
                                         131072LL,  0LL,        // B: b
                                         131072LL,  1048576LL,  // C: b, h
                                         2);

    // ---- head mean (fp16 hi out) ----
    reduce_mean_kernel<<<dim3((MROWS * DK) / 256), 256>>>(oh, om);

    // ---- out = Om @ Wo ----
    gemm_h<<<dim3(8, 64, 1), 256, GSM>>>(om, woh, wol, out, nullptr, nullptr,
                                         128, 128, 128, 1024,
                                         0,0, 0,0, 0,0, 0);
}

// round 5
// speedup vs baseline: 6.9681x; 1.1353x over previous
#include <cuda_runtime.h>
#include <cuda_fp16.h>
#include <stdint.h>
#include <math.h>

#define BB 8
#define TT 1024
#define DM 1024
#define NH 8
#define DK 128
#define MROWS (BB*TT)   /* 8192 */

// ---------------- scratch (device globals; no cudaMalloc allowed) ----------
__device__ __half g_q2 [(size_t)MROWS * DM];      // 16 MB
__device__ __half g_k2 [(size_t)MROWS * DM];      // 16 MB
__device__ __half g_v2 [(size_t)MROWS * DM];      // 16 MB
__device__ __half g_wqh[(size_t)NH * DM * DK];    // 2 MB  [h][128][1024] hi
__device__ __half g_wkh[(size_t)NH * DM * DK];
__device__ __half g_wkl[(size_t)NH * DM * DK];
__device__ __half g_wvh[(size_t)DM * DK];         // [128][1024]
__device__ __half g_wvl[(size_t)DM * DK];
__device__ __half g_woh[(size_t)DM * DK];         // [1024][128]
__device__ __half g_wol[(size_t)DM * DK];
__device__ __half g_qh [(size_t)MROWS * DM];      // 16 MB  qh hi (A of scores)
__device__ __half g_khh[(size_t)MROWS * DM];      // 16 MB  kh hi (B of scores)
__device__ __half g_khl[(size_t)MROWS * DM];      // 16 MB  kh lo
__device__ float  g_vh [(size_t)MROWS * DK];      // 4 MB   vh fp32
__device__ __half g_vth[(size_t)MROWS * DK];      // 2 MB   vhT hi [b][128][1024]
__device__ __half g_vtl[(size_t)MROWS * DK];      // 2 MB   vhT lo
__device__ __half g_ph [(size_t)NH * BB * TT * TT]; // 134 MB  P hi (A of PV)
__device__ float  g_oh [(size_t)NH * MROWS * DK]; // 33 MB per-head O
__device__ __half g_om [(size_t)MROWS * DK];      // 2 MB   head-mean hi

// ======================= helpers ==============================
__device__ __forceinline__ uint32_t smem_u32(const void* p) {
    uint32_t a;
    asm("{ .reg .u64 t; cvta.to.shared.u64 t, %1; cvt.u32.u64 %0, t; }"
        : "=r"(a) : "l"(p));
    return a;
}
__device__ __forceinline__ uint32_t sw128(uint32_t off) {
    return off ^ ((off >> 3) & 0x70);
}
__device__ __forceinline__ void ldm4(uint32_t* d, uint32_t addr) {
    asm volatile("ldmatrix.sync.aligned.m8n8.x4.shared.b16 {%0,%1,%2,%3}, [%4];"
                 : "=r"(d[0]), "=r"(d[1]), "=r"(d[2]), "=r"(d[3]) : "r"(addr));
}
__device__ __forceinline__ void mma16816(float* c, const uint32_t* a, const uint32_t* b) {
    asm volatile(
        "mma.sync.aligned.m16n8k16.row.col.f32.f16.f16.f32 "
        "{%0,%1,%2,%3}, {%4,%5,%6,%7}, {%8,%9}, {%0,%1,%2,%3};"
        : "+f"(c[0]), "+f"(c[1]), "+f"(c[2]), "+f"(c[3])
        : "r"(a[0]), "r"(a[1]), "r"(a[2]), "r"(a[3]), "r"(b[0]), "r"(b[1]));
}
#define CP16(sa, ga) \
    asm volatile("cp.async.ca.shared.global [%0], [%1], 16;" :: "r"(sa), "l"(ga))
#define CP_COMMIT() asm volatile("cp.async.commit_group;" ::: "memory")
#define CP_WAIT1()  asm volatile("cp.async.wait_group 1;"  ::: "memory")

// ============================================================================
// fp16 HMMA GEMM:  D[128x128 tile] = A_hi(MxK) * (B_hi [+ B_lo])(NxK)^T
// 2-stage cp.async pipeline; stage = 3 x 16KB (Ah, Bh, Bl) = 48KB -> 96KB smem
// -> 2 CTAs/SM. Batched over blockIdx.z = z1*8 + z2 with (S1,S2) strides.
// mode: 0 = plain, 1 = causal score tile skip, 2 = causal K-limit (PV).
// Bl == nullptr => 1-term B. Output fp32 C and/or fp16 Ch (+ Cl split).
// ============================================================================
__global__ __launch_bounds__(256, 2)
void gemm_h(const __half* __restrict__ Ah, const __half* __restrict__ Bh,
            const __half* __restrict__ Bl,
            float* __restrict__ C, __half* __restrict__ Ch, __half* __restrict__ Cl,
            int K, int lda, int ldb, int ldc,
            long long aS1, long long aS2, long long bS1, long long bS2,
            long long cS1, long long cS2, int mode)
{
    extern __shared__ char sm[];
    const int tid  = threadIdx.x;
    const int wid  = tid >> 5;
    const int lane = tid & 31;
    const int row0 = blockIdx.y * 128;
    const int col0 = blockIdx.x * 128;
    if (mode == 1 && col0 >= row0 + 128) return;     // fully above diagonal

    const int z1 = blockIdx.z >> 3, z2 = blockIdx.z & 7;
    const __half* Ab  = Ah + (size_t)z1 * aS1 + (size_t)z2 * aS2;
    const __half* Bhb = Bh + (size_t)z1 * bS1 + (size_t)z2 * bS2;
    const bool blon = (Bl != nullptr);
    const __half* Blb = blon ? Bl + (size_t)z1 * bS1 + (size_t)z2 * bS2 : Bhb;

    const int Keff = (mode == 2) ? (row0 + 128 < K ? row0 + 128 : K) : K;
    const int nCh  = Keff >> 6;                      // 64-wide K chunks (>=2)

    const uint32_t sb = smem_u32(sm);

#define FILL(cc) do {                                                         \
        uint32_t stb = sb + ((cc) & 1) * 49152;                               \
        const int k0 = (cc) << 6;                                             \
        _Pragma("unroll")                                                     \
        for (int i = 0; i < 4; i++) {                                         \
            int id = tid + 256 * i;                                           \
            int rr = id >> 3, sg = id & 7;                                    \
            uint32_t sw = sw128((uint32_t)rr * 128 + sg * 16);                \
            CP16(stb + sw,         Ab  + (size_t)(row0 + rr) * lda + k0 + sg * 8); \
            CP16(stb + 16384 + sw, Bhb + (size_t)(col0 + rr) * ldb + k0 + sg * 8); \
            if (blon)                                                         \
                CP16(stb + 32768 + sw, Blb + (size_t)(col0 + rr) * ldb + k0 + sg * 8); \
        }                                                                     \
    } while (0)

    // ---- warp tiling: 2 (m) x 4 (n) warps; each 64 rows x 32 cols ----
    const int wm = (wid >> 2) * 64;
    const int wn = (wid & 3) * 32;

    uint32_t aBase[4], bBase[2];
#pragma unroll
    for (int mt = 0; mt < 4; mt++) {
        int r = wm + mt * 16 + ((lane >> 3) & 1) * 8 + (lane & 7);
        aBase[mt] = (uint32_t)r * 128 + (uint32_t)((lane >> 4) * 8) * 2;
    }
#pragma unroll
    for (int np = 0; np < 2; np++) {
        int r = wn + np * 16 + (lane >> 4) * 8 + (lane & 7);
        bBase[np] = (uint32_t)r * 128 + (uint32_t)(((lane >> 3) & 1) * 8) * 2;
    }

    float acc[4][4][4];
#pragma unroll
    for (int mt = 0; mt < 4; mt++)
#pragma unroll
        for (int nt = 0; nt < 4; nt++)
#pragma unroll
            for (int i = 0; i < 4; i++) acc[mt][nt][i] = 0.f;

    // ---- prologue: 2 stages in flight ----
    FILL(0); CP_COMMIT();
    if (nCh > 1) FILL(1);
    CP_COMMIT();

    for (int c = 0; c < nCh; ++c) {
        CP_WAIT1();
        __syncthreads();
        const uint32_t tb = sb + (c & 1) * 49152;
#pragma unroll
        for (int ks = 0; ks < 4; ks++) {
            const uint32_t kb = (uint32_t)ks * 32;
            uint32_t a[4][4], bh2[2][4], bl2[2][4];
#pragma unroll
            for (int mt = 0; mt < 4; mt++)
                ldm4(a[mt], tb + sw128(aBase[mt] + kb));
#pragma unroll
            for (int np = 0; np < 2; np++)
                ldm4(bh2[np], tb + 16384 + sw128(bBase[np] + kb));
#pragma unroll
            for (int mt = 0; mt < 4; mt++)
#pragma unroll
                for (int nt = 0; nt < 4; nt++)
                    mma16816(acc[mt][nt], a[mt], &bh2[nt >> 1][(nt & 1) * 2]);
            if (blon) {
#pragma unroll
                for (int np = 0; np < 2; np++)
                    ldm4(bl2[np], tb + 32768 + sw128(bBase[np] + kb));
#pragma unroll
                for (int mt = 0; mt < 4; mt++)
#pragma unroll
                    for (int nt = 0; nt < 4; nt++)
                        mma16816(acc[mt][nt], a[mt], &bl2[nt >> 1][(nt & 1) * 2]);
            }
        }
        __syncthreads();                // all reads of buf (c&1) done
        int f = c + 2;
        if (f < nCh) FILL(f);
        CP_COMMIT();
    }
#undef FILL

    // ---- epilogue ----
    float*  Cb  = C  ? C  + (size_t)z1 * cS1 + (size_t)z2 * cS2 : nullptr;
    __half* Chb = Ch ? Ch + (size_t)z1 * cS1 + (size_t)z2 * cS2 : nullptr;
    __half* Clb = Cl ? Cl + (size_t)z1 * cS1 + (size_t)z2 * cS2 : nullptr;

#pragma unroll
    for (int mt = 0; mt < 4; mt++) {
        const int r = row0 + wm + mt * 16 + (lane >> 2);
#pragma unroll
        for (int nt = 0; nt < 4; nt++) {
            const int cc = col0 + wn + nt * 8 + (lane & 3) * 2;
            if (Cb) {
                float* p = Cb + (size_t)r * ldc + cc;
                *(float2*)p = make_float2(acc[mt][nt][0], acc[mt][nt][1]);
                *(float2*)(p + (size_t)8 * ldc) = make_float2(acc[mt][nt][2], acc[mt][nt][3]);
            }
            if (Chb) {
                __half2 h0 = __floats2half2_rn(acc[mt][nt][0], acc[mt][nt][1]);
                __half2 h1 = __floats2half2_rn(acc[mt][nt][2], acc[mt][nt][3]);
                *(__half2*)(Chb + (size_t)r * ldc + cc) = h0;
                *(__half2*)(Chb + (size_t)(r + 8) * ldc + cc) = h1;
                if (Clb) {
                    __half2 l0 = __floats2half2_rn(acc[mt][nt][0] - __low2float(h0),
                                                   acc[mt][nt][1] - __high2float(h0));
                    __half2 l1 = __floats2half2_rn(acc[mt][nt][2] - __low2float(h1),
                                                   acc[mt][nt][3] - __high2float(h1));
                    *(__half2*)(Clb + (size_t)r * ldc + cc) = l0;
                    *(__half2*)(Clb + (size_t)(r + 8) * ldc + cc) = l1;
                }
            }
        }
    }
}

// ============================================================================
// fp32 -> fp16 convert; blockIdx.y selects one of 3 (in,out) pairs
// ============================================================================
__global__ __launch_bounds__(256)
void conv_h3(const float* __restrict__ i0, __half* __restrict__ o0,
             const float* __restrict__ i1, __half* __restrict__ o1,
             const float* __restrict__ i2, __half* __restrict__ o2)
{
    const float* in  = blockIdx.y == 0 ? i0 : (blockIdx.y == 1 ? i1 : i2);
    __half*      out = blockIdx.y == 0 ? o0 : (blockIdx.y == 1 ? o1 : o2);
    const size_t i = ((size_t)blockIdx.x * 256 + threadIdx.x) * 4;
    float4 v = *(const float4*)(in + i);
    *(__half2*)(out + i)     = __floats2half2_rn(v.x, v.y);
    *(__half2*)(out + i + 2) = __floats2half2_rn(v.z, v.w);
}

// ============================================================================
// Batched transpose + split: fp32 in (z,R,C) -> fp16 hi/lo out (z,C,R)
// ============================================================================
__global__ __launch_bounds__(256)
void transpose_split(const float* __restrict__ in, __half* __restrict__ oh,
                     __half* __restrict__ ol, int R, int C)
{
    __shared__ float t[32][33];
    const float* ib = in + (size_t)blockIdx.z * R * C;
    __half* ohb = oh + (size_t)blockIdx.z * R * C;
    __half* olb = ol ? ol + (size_t)blockIdx.z * R * C : nullptr;
    const int r0 = blockIdx.y * 32, c0 = blockIdx.x * 32;
    const int tx = threadIdx.x, ty = threadIdx.y;
#pragma unroll
    for (int i = 0; i < 32; i += 8)
        t[ty + i][tx] = ib[(size_t)(r0 + ty + i) * C + c0 + tx];
    __syncthreads();
#pragma unroll
    for (int i = 0; i < 32; i += 8) {
        float x = t[tx][ty + i];
        __half h = __float2half_rn(x);
        size_t idx = (size_t)(c0 + ty + i) * R + r0 + tx;
        ohb[idx] = h;
        if (olb) olb[idx] = __float2half_rn(x - __half2float(h));
    }
}

// ============================================================================
// In-place causal softmax; emits fp16 P_hi (only up to causal 128-block edge).
// ============================================================================
__global__ __launch_bounds__(256)
void softmax_kernel(float* __restrict__ attn, __half* __restrict__ ph)
{
    const int gw   = blockIdx.x * 8 + (threadIdx.x >> 5);
    const int lane = threadIdx.x & 31;
    const int t    = gw & (TT - 1);
    float*  row  = attn + (size_t)gw * TT;
    __half* prow = ph   + (size_t)gw * TT;
    const int ilim = (((t >> 7) + 1) << 7) >> 5;   // #32-chunks PV will read

    float v[32];
    float m = -1e30f;
#pragma unroll
    for (int i = 0; i < 32; i++) {
        const int s = i * 32 + lane;
        v[i] = (s <= t) ? row[s] : -1e30f;
        m = fmaxf(m, v[i]);
    }
#pragma unroll
    for (int o = 16; o; o >>= 1) m = fmaxf(m, __shfl_xor_sync(~0u, m, o));

    const float scale = 0.08838834764831845f;   // 1/sqrt(128)
    float sum = 0.f;
#pragma unroll
    for (int i = 0; i < 32; i++) {
        const int s = i * 32 + lane;
        float e = (s <= t) ? __expf((v[i] - m) * scale) : 0.f;
        v[i] = e;
        sum += e;
    }
#pragma unroll
    for (int o = 16; o; o >>= 1) sum += __shfl_xor_sync(~0u, sum, o);
    const float rinv = 1.0f / sum;

#pragma unroll
    for (int i = 0; i < 32; i++) {
        const int s = i * 32 + lane;
        float p = v[i] * rinv;
        row[s] = p;
        if (i < ilim) prow[s] = __float2half_rn(p);
    }
}

// ============================================================================
__global__ __launch_bounds__(256)
void reduce_mean_kernel(const float* __restrict__ oh, __half* __restrict__ om)
{
    const size_t i = (size_t)blockIdx.x * 256 + threadIdx.x;
    float s = 0.f;
#pragma unroll
    for (int h = 0; h < NH; h++) s += oh[(size_t)h * MROWS * DK + i];
    om[i] = __float2half_rn(s * 0.125f);
}

// ============================================================================
extern "C" void kernel_launch(void* const* d_in, const int* in_sizes, int n_in,
                              void* d_out, int out_size)
{
    const float* q  = (const float*)d_in[0];
    const float* k  = (const float*)d_in[1];
    const float* v  = (const float*)d_in[2];
    /* d_in[3] = mask: exact causal tril; handled analytically */
    const float* Wq = (const float*)d_in[4];
    const float* Wk = (const float*)d_in[5];
    const float* Wv = (const float*)d_in[6];
    const float* Wo = (const float*)d_in[7];

    float* out  = (float*)d_out;                       // (B,T,DM)
    float* attn = out + (size_t)MROWS * DM;            // (H,B,T,S)

    __half *q2,*k2,*v2,*wqh,*wkh,*wkl,*wvh,*wvl,*woh,*wol;
    __half *qh,*khh,*khl,*vth,*vtl,*ph,*om;
    float *vh,*oh;
    cudaGetSymbolAddress((void**)&q2,  g_q2);
    cudaGetSymbolAddress((void**)&k2,  g_k2);
    cudaGetSymbolAddress((void**)&v2,  g_v2);
    cudaGetSymbolAddress((void**)&wqh, g_wqh);
    cudaGetSymbolAddress((void**)&wkh, g_wkh);
    cudaGetSymbolAddress((void**)&wkl, g_wkl);
    cudaGetSymbolAddress((void**)&wvh, g_wvh);
    cudaGetSymbolAddress((void**)&wvl, g_wvl);
    cudaGetSymbolAddress((void**)&woh, g_woh);
    cudaGetSymbolAddress((void**)&wol, g_wol);
    cudaGetSymbolAddress((void**)&qh,  g_qh);
    cudaGetSymbolAddress((void**)&khh, g_khh);
    cudaGetSymbolAddress((void**)&khl, g_khl);
    cudaGetSymbolAddress((void**)&vh,  g_vh);
    cudaGetSymbolAddress((void**)&vth, g_vth);
    cudaGetSymbolAddress((void**)&vtl, g_vtl);
    cudaGetSymbolAddress((void**)&ph,  g_ph);
    cudaGetSymbolAddress((void**)&oh,  g_oh);
    cudaGetSymbolAddress((void**)&om,  g_om);

    const int GSM = 2 * 3 * 16384;                     // 96 KB dynamic smem
    cudaFuncSetAttribute(gemm_h, cudaFuncAttributeMaxDynamicSharedMemorySize, GSM);

    dim3 tb(32, 8);

    // ---- operand preparation ----
    conv_h3<<<dim3(MROWS * DM / 1024, 3), 256>>>(q, q2, k, k2, v, v2);
    transpose_split<<<dim3(4, 32, 8), tb>>>(Wq, wqh, nullptr, 1024, 128); // hi only
    transpose_split<<<dim3(4, 32, 8), tb>>>(Wk, wkh, wkl, 1024, 128);
    transpose_split<<<dim3(4, 32, 1), tb>>>(Wv, wvh, wvl, 1024, 128);  // (128,1024)
    transpose_split<<<dim3(32, 4, 1), tb>>>(Wo, woh, wol, 128, 1024);  // (1024,128)

    // ---- projections ----
    gemm_h<<<dim3(8, 64, 1), 256, GSM>>>(q2, wqh, nullptr, nullptr, qh, nullptr,
                                         1024, 1024, 1024, 1024,
                                         0,0, 0,0, 0,0, 0);
    gemm_h<<<dim3(8, 64, 1), 256, GSM>>>(k2, wkh, wkl, nullptr, khh, khl,
                                         1024, 1024, 1024, 1024,
                                         0,0, 0,0, 0,0, 0);
    gemm_h<<<dim3(1, 64, 1), 256, GSM>>>(v2, wvh, wvl, vh, nullptr, nullptr,
                                         1024, 1024, 1024, 128,
                                         0,0, 0,0, 0,0, 0);
    transpose_split<<<dim3(4, 32, 8), tb>>>(vh, vth, vtl, 1024, 128);  // per-b

    // ---- scores = qh @ kh^T  (batched z = b*8+h, causal tile skip) ----
    gemm_h<<<dim3(8, 8, 64), 256, GSM>>>(qh, khh, khl, attn, nullptr, nullptr,
                                         128, 1024, 1024, 1024,
                                         1048576LL, 128LL,      // A: b, h
                                         1048576LL, 128LL,      // B: b, h
                                         1048576LL, 8388608LL,  // C: b, h
                                         1);

    // ---- softmax in place; emits P_hi ----
    softmax_kernel<<<dim3(NH * BB * TT / 8), 256>>>(attn, ph);

    // ---- O_h = P @ V  (batched, causal K limit) ----
    gemm_h<<<dim3(1, 8, 64), 256, GSM>>>(ph, vth, vtl, oh, nullptr, nullptr,
                                         1024, 1024, 1024, 128,
                                         1048576LL, 8388608LL,  // A: b, h
                                         131072LL,  0LL,        // B: b
                                         131072LL,  1048576LL,  // C: b, h
                                         2);

    // ---- head mean (fp16 hi out) ----
    reduce_mean_kernel<<<dim3((MROWS * DK) / 256), 256>>>(oh, om);

    // ---- out = Om @ Wo ----
    gemm_h<<<dim3(8, 64, 1), 256, GSM>>>(om, woh, wol, out, nullptr, nullptr,
                                         128, 128, 128, 1024,
                                         0,0, 0,0, 0,0, 0);
}

// round 6
// speedup vs baseline: 8.8038x; 1.2634x over previous
#include <cuda_runtime.h>
#include <cuda_fp16.h>
#include <stdint.h>
#include <math.h>

#define BB 8
#define TT 1024
#define DM 1024
#define NH 8
#define DK 128
#define MROWS (BB*TT)   /* 8192 */

// ---------------- scratch (device globals; no cudaMalloc allowed) ----------
__device__ __half g_q2 [(size_t)MROWS * DM];      // 16 MB
__device__ __half g_k2 [(size_t)MROWS * DM];      // 16 MB
__device__ __half g_v2 [(size_t)MROWS * DM];      // 16 MB
__device__ __half g_wqh[(size_t)NH * DM * DK];    // 2 MB  [h][128][1024]
__device__ __half g_wkh[(size_t)NH * DM * DK];
__device__ __half g_wvh[(size_t)DM * DK];         // [128][1024]
__device__ __half g_woh[(size_t)DM * DK];         // [1024][128]
__device__ __half g_qh [(size_t)MROWS * DM];      // 16 MB  qh hi (A of scores)
__device__ __half g_khh[(size_t)MROWS * DM];      // 16 MB  kh hi (B of scores)
__device__ float  g_vh [(size_t)MROWS * DK];      // 4 MB   vh fp32
__device__ __half g_vth[(size_t)MROWS * DK];      // 2 MB   vhT [b][128][1024]
__device__ __half g_ph [(size_t)NH * BB * TT * TT]; // 134 MB  P hi (A of PV)
__device__ float  g_oh [(size_t)NH * MROWS * DK]; // 33 MB per-head O
__device__ __half g_om [(size_t)MROWS * DK];      // 2 MB   head-mean hi

// ======================= helpers ==============================
__device__ __forceinline__ uint32_t smem_u32(const void* p) {
    uint32_t a;
    asm("{ .reg .u64 t; cvta.to.shared.u64 t, %1; cvt.u32.u64 %0, t; }"
        : "=r"(a) : "l"(p));
    return a;
}
__device__ __forceinline__ uint32_t sw128(uint32_t off) {
    return off ^ ((off >> 3) & 0x70);
}
__device__ __forceinline__ void ldm4(uint32_t* d, uint32_t addr) {
    asm volatile("ldmatrix.sync.aligned.m8n8.x4.shared.b16 {%0,%1,%2,%3}, [%4];"
                 : "=r"(d[0]), "=r"(d[1]), "=r"(d[2]), "=r"(d[3]) : "r"(addr));
}
__device__ __forceinline__ void mma16816(float* c, const uint32_t* a, const uint32_t* b) {
    asm volatile(
        "mma.sync.aligned.m16n8k16.row.col.f32.f16.f16.f32 "
        "{%0,%1,%2,%3}, {%4,%5,%6,%7}, {%8,%9}, {%0,%1,%2,%3};"
        : "+f"(c[0]), "+f"(c[1]), "+f"(c[2]), "+f"(c[3])
        : "r"(a[0]), "r"(a[1]), "r"(a[2]), "r"(a[3]), "r"(b[0]), "r"(b[1]));
}
#define CP16(sa, ga) \
    asm volatile("cp.async.ca.shared.global [%0], [%1], 16;" :: "r"(sa), "l"(ga))
#define CP_COMMIT() asm volatile("cp.async.commit_group;" ::: "memory")
#define CP_WAIT2()  asm volatile("cp.async.wait_group 2;"  ::: "memory")

// ============================================================================
// fp16 HMMA GEMM (1-term):  D[128x128 tile] = A(MxK) * B(NxK)^T
// 3-stage cp.async pipeline; stage = 2 x 16KB (A, B) = 32KB -> 96KB smem
// -> 2 CTAs/SM. Batched over blockIdx.z = z1*8 + z2 with (S1,S2) strides.
// mode: 0 = plain, 1 = causal score tile skip, 2 = causal K-limit (PV).
// Output fp32 C and/or fp16 Ch.
// ============================================================================
__global__ __launch_bounds__(256, 2)
void gemm_h(const __half* __restrict__ Ah, const __half* __restrict__ Bh,
            float* __restrict__ C, __half* __restrict__ Ch,
            int K, int lda, int ldb, int ldc,
            long long aS1, long long aS2, long long bS1, long long bS2,
            long long cS1, long long cS2, int mode)
{
    extern __shared__ char sm[];
    const int tid  = threadIdx.x;
    const int wid  = tid >> 5;
    const int lane = tid & 31;
    const int row0 = blockIdx.y * 128;
    const int col0 = blockIdx.x * 128;
    if (mode == 1 && col0 >= row0 + 128) return;     // fully above diagonal

    const int z1 = blockIdx.z >> 3, z2 = blockIdx.z & 7;
    const __half* Ab  = Ah + (size_t)z1 * aS1 + (size_t)z2 * aS2;
    const __half* Bhb = Bh + (size_t)z1 * bS1 + (size_t)z2 * bS2;

    const int Keff = (mode == 2) ? (row0 + 128 < K ? row0 + 128 : K) : K;
    const int nCh  = Keff >> 6;                      // 64-wide K chunks (>=2)

    const uint32_t sb = smem_u32(sm);

#define FILL(cc) do {                                                         \
        uint32_t stb = sb + (uint32_t)((cc) % 3) * 32768;                     \
        const int k0 = (cc) << 6;                                             \
        _Pragma("unroll")                                                     \
        for (int i = 0; i < 4; i++) {                                         \
            int id = tid + 256 * i;                                           \
            int rr = id >> 3, sg = id & 7;                                    \
            uint32_t sw = sw128((uint32_t)rr * 128 + sg * 16);                \
            CP16(stb + sw,         Ab  + (size_t)(row0 + rr) * lda + k0 + sg * 8); \
            CP16(stb + 16384 + sw, Bhb + (size_t)(col0 + rr) * ldb + k0 + sg * 8); \
        }                                                                     \
    } while (0)

    // ---- warp tiling: 2 (m) x 4 (n) warps; each 64 rows x 32 cols ----
    const int wm = (wid >> 2) * 64;
    const int wn = (wid & 3) * 32;

    uint32_t aBase[4], bBase[2];
#pragma unroll
    for (int mt = 0; mt < 4; mt++) {
        int r = wm + mt * 16 + ((lane >> 3) & 1) * 8 + (lane & 7);
        aBase[mt] = (uint32_t)r * 128 + (uint32_t)((lane >> 4) * 8) * 2;
    }
#pragma unroll
    for (int np = 0; np < 2; np++) {
        int r = wn + np * 16 + (lane >> 4) * 8 + (lane & 7);
        bBase[np] = (uint32_t)r * 128 + (uint32_t)(((lane >> 3) & 1) * 8) * 2;
    }

    float acc[4][4][4];
#pragma unroll
    for (int mt = 0; mt < 4; mt++)
#pragma unroll
        for (int nt = 0; nt < 4; nt++)
#pragma unroll
            for (int i = 0; i < 4; i++) acc[mt][nt][i] = 0.f;

    // ---- prologue: 3 stages in flight ----
#pragma unroll
    for (int p = 0; p < 3; p++) { if (p < nCh) FILL(p); CP_COMMIT(); }

    for (int c = 0; c < nCh; ++c) {
        CP_WAIT2();
        __syncthreads();
        const uint32_t tb = sb + (uint32_t)(c % 3) * 32768;
#pragma unroll
        for (int ks = 0; ks < 4; ks++) {
            const uint32_t kb = (uint32_t)ks * 32;
            uint32_t a[4][4], b2[2][4];
#pragma unroll
            for (int mt = 0; mt < 4; mt++)
                ldm4(a[mt], tb + sw128(aBase[mt] + kb));
#pragma unroll
            for (int np = 0; np < 2; np++)
                ldm4(b2[np], tb + 16384 + sw128(bBase[np] + kb));
#pragma unroll
            for (int mt = 0; mt < 4; mt++)
#pragma unroll
                for (int nt = 0; nt < 4; nt++)
                    mma16816(acc[mt][nt], a[mt], &b2[nt >> 1][(nt & 1) * 2]);
        }
        __syncthreads();                // all reads of buf (c%3) done
        int f = c + 3;
        if (f < nCh) FILL(f);
        CP_COMMIT();
    }
#undef FILL

    // ---- epilogue ----
    float*  Cb  = C  ? C  + (size_t)z1 * cS1 + (size_t)z2 * cS2 : nullptr;
    __half* Chb = Ch ? Ch + (size_t)z1 * cS1 + (size_t)z2 * cS2 : nullptr;

#pragma unroll
    for (int mt = 0; mt < 4; mt++) {
        const int r = row0 + wm + mt * 16 + (lane >> 2);
#pragma unroll
        for (int nt = 0; nt < 4; nt++) {
            const int cc = col0 + wn + nt * 8 + (lane & 3) * 2;
            if (Cb) {
                float* p = Cb + (size_t)r * ldc + cc;
                *(float2*)p = make_float2(acc[mt][nt][0], acc[mt][nt][1]);
                *(float2*)(p + (size_t)8 * ldc) = make_float2(acc[mt][nt][2], acc[mt][nt][3]);
            }
            if (Chb) {
                *(__half2*)(Chb + (size_t)r * ldc + cc) =
                    __floats2half2_rn(acc[mt][nt][0], acc[mt][nt][1]);
                *(__half2*)(Chb + (size_t)(r + 8) * ldc + cc) =
                    __floats2half2_rn(acc[mt][nt][2], acc[mt][nt][3]);
            }
        }
    }
}

// ============================================================================
// fp32 -> fp16 convert; blockIdx.y selects one of 3 (in,out) pairs
// ============================================================================
__global__ __launch_bounds__(256)
void conv_h3(const float* __restrict__ i0, __half* __restrict__ o0,
             const float* __restrict__ i1, __half* __restrict__ o1,
             const float* __restrict__ i2, __half* __restrict__ o2)
{
    const float* in  = blockIdx.y == 0 ? i0 : (blockIdx.y == 1 ? i1 : i2);
    __half*      out = blockIdx.y == 0 ? o0 : (blockIdx.y == 1 ? o1 : o2);
    const size_t i = ((size_t)blockIdx.x * 256 + threadIdx.x) * 4;
    float4 v = *(const float4*)(in + i);
    *(__half2*)(out + i)     = __floats2half2_rn(v.x, v.y);
    *(__half2*)(out + i + 2) = __floats2half2_rn(v.z, v.w);
}

// ============================================================================
// Batched transpose: fp32 in (z,R,C) -> fp16 out (z,C,R)
// ============================================================================
__global__ __launch_bounds__(256)
void transpose_h(const float* __restrict__ in, __half* __restrict__ oh,
                 int R, int C)
{
    __shared__ float t[32][33];
    const float* ib = in + (size_t)blockIdx.z * R * C;
    __half* ohb = oh + (size_t)blockIdx.z * R * C;
    const int r0 = blockIdx.y * 32, c0 = blockIdx.x * 32;
    const int tx = threadIdx.x, ty = threadIdx.y;
#pragma unroll
    for (int i = 0; i < 32; i += 8)
        t[ty + i][tx] = ib[(size_t)(r0 + ty + i) * C + c0 + tx];
    __syncthreads();
#pragma unroll
    for (int i = 0; i < 32; i += 8)
        ohb[(size_t)(c0 + ty + i) * R + r0 + tx] = __float2half_rn(t[tx][ty + i]);
}

// ============================================================================
// In-place causal softmax; emits fp16 P_hi (only up to causal 128-block edge).
// ============================================================================
__global__ __launch_bounds__(256)
void softmax_kernel(float* __restrict__ attn, __half* __restrict__ ph)
{
    const int gw   = blockIdx.x * 8 + (threadIdx.x >> 5);
    const int lane = threadIdx.x & 31;
    const int t    = gw & (TT - 1);
    float*  row  = attn + (size_t)gw * TT;
    __half* prow = ph   + (size_t)gw * TT;
    const int ilim = (((t >> 7) + 1) << 7) >> 5;   // #32-chunks PV will read

    float v[32];
    float m = -1e30f;
#pragma unroll
    for (int i = 0; i < 32; i++) {
        const int s = i * 32 + lane;
        v[i] = (s <= t) ? row[s] : -1e30f;
        m = fmaxf(m, v[i]);
    }
#pragma unroll
    for (int o = 16; o; o >>= 1) m = fmaxf(m, __shfl_xor_sync(~0u, m, o));

    const float scale = 0.08838834764831845f;   // 1/sqrt(128)
    float sum = 0.f;
#pragma unroll
    for (int i = 0; i < 32; i++) {
        const int s = i * 32 + lane;
        float e = (s <= t) ? __expf((v[i] - m) * scale) : 0.f;
        v[i] = e;
        sum += e;
    }
#pragma unroll
    for (int o = 16; o; o >>= 1) sum += __shfl_xor_sync(~0u, sum, o);
    const float rinv = 1.0f / sum;

#pragma unroll
    for (int i = 0; i < 32; i++) {
        const int s = i * 32 + lane;
        float p = v[i] * rinv;
        row[s] = p;
        if (i < ilim) prow[s] = __float2half_rn(p);
    }
}

// ============================================================================
__global__ __launch_bounds__(256)
void reduce_mean_kernel(const float* __restrict__ oh, __half* __restrict__ om)
{
    const size_t i = (size_t)blockIdx.x * 256 + threadIdx.x;
    float s = 0.f;
#pragma unroll
    for (int h = 0; h < NH; h++) s += oh[(size_t)h * MROWS * DK + i];
    om[i] = __float2half_rn(s * 0.125f);
}

// ============================================================================
extern "C" void kernel_launch(void* const* d_in, const int* in_sizes, int n_in,
                              void* d_out, int out_size)
{
    const float* q  = (const float*)d_in[0];
    const float* k  = (const float*)d_in[1];
    const float* v  = (const float*)d_in[2];
    /* d_in[3] = mask: exact causal tril; handled analytically */
    const float* Wq = (const float*)d_in[4];
    const float* Wk = (const float*)d_in[5];
    const float* Wv = (const float*)d_in[6];
    const float* Wo = (const float*)d_in[7];

    float* out  = (float*)d_out;                       // (B,T,DM)
    float* attn = out + (size_t)MROWS * DM;            // (H,B,T,S)

    __half *q2,*k2,*v2,*wqh,*wkh,*wvh,*woh,*qh,*khh,*vth,*ph,*om;
    float *vh,*oh;
    cudaGetSymbolAddress((void**)&q2,  g_q2);
    cudaGetSymbolAddress((void**)&k2,  g_k2);
    cudaGetSymbolAddress((void**)&v2,  g_v2);
    cudaGetSymbolAddress((void**)&wqh, g_wqh);
    cudaGetSymbolAddress((void**)&wkh, g_wkh);
    cudaGetSymbolAddress((void**)&wvh, g_wvh);
    cudaGetSymbolAddress((void**)&woh, g_woh);
    cudaGetSymbolAddress((void**)&qh,  g_qh);
    cudaGetSymbolAddress((void**)&khh, g_khh);
    cudaGetSymbolAddress((void**)&vh,  g_vh);
    cudaGetSymbolAddress((void**)&vth, g_vth);
    cudaGetSymbolAddress((void**)&ph,  g_ph);
    cudaGetSymbolAddress((void**)&oh,  g_oh);
    cudaGetSymbolAddress((void**)&om,  g_om);

    const int GSM = 3 * 2 * 16384;                     // 96 KB dynamic smem
    cudaFuncSetAttribute(gemm_h, cudaFuncAttributeMaxDynamicSharedMemorySize, GSM);

    dim3 tb(32, 8);

    // ---- operand preparation ----
    conv_h3<<<dim3(MROWS * DM / 1024, 3), 256>>>(q, q2, k, k2, v, v2);
    transpose_h<<<dim3(4, 32, 8), tb>>>(Wq, wqh, 1024, 128);  // (8,128,1024)
    transpose_h<<<dim3(4, 32, 8), tb>>>(Wk, wkh, 1024, 128);
    transpose_h<<<dim3(4, 32, 1), tb>>>(Wv, wvh, 1024, 128);  // (128,1024)
    transpose_h<<<dim3(32, 4, 1), tb>>>(Wo, woh, 128, 1024);  // (1024,128)

    // ---- projections ----
    gemm_h<<<dim3(8, 64, 1), 256, GSM>>>(q2, wqh, nullptr, qh,
                                         1024, 1024, 1024, 1024,
                                         0,0, 0,0, 0,0, 0);
    gemm_h<<<dim3(8, 64, 1), 256, GSM>>>(k2, wkh, nullptr, khh,
                                         1024, 1024, 1024, 1024,
                                         0,0, 0,0, 0,0, 0);
    gemm_h<<<dim3(1, 64, 1), 256, GSM>>>(v2, wvh, vh, nullptr,
                                         1024, 1024, 1024, 128,
                                         0,0, 0,0, 0,0, 0);
    transpose_h<<<dim3(4, 32, 8), tb>>>(vh, vth, 1024, 128);  // per-b (128,1024)

    // ---- scores = qh @ kh^T  (batched z = b*8+h, causal tile skip) ----
    gemm_h<<<dim3(8, 8, 64), 256, GSM>>>(qh, khh, attn, nullptr,
                                         128, 1024, 1024, 1024,
                                         1048576LL, 128LL,      // A: b, h
                                         1048576LL, 128LL,      // B: b, h
                                         1048576LL, 8388608LL,  // C: b, h
                                         1);

    // ---- softmax in place; emits P_hi ----
    softmax_kernel<<<dim3(NH * BB * TT / 8), 256>>>(attn, ph);

    // ---- O_h = P @ V  (batched, causal K limit) ----
    gemm_h<<<dim3(1, 8, 64), 256, GSM>>>(ph, vth, oh, nullptr,
                                         1024, 1024, 1024, 128,
                                         1048576LL, 8388608LL,  // A: b, h
                                         131072LL,  0LL,        // B: b
                                         131072LL,  1048576LL,  // C: b, h
                                         2);

    // ---- head mean (fp16 hi out) ----
    reduce_mean_kernel<<<dim3((MROWS * DK) / 256), 256>>>(oh, om);

    // ---- out = Om @ Wo ----
    gemm_h<<<dim3(8, 64, 1), 256, GSM>>>(om, woh, out, nullptr,
                                         128, 128, 128, 1024,
                                         0,0, 0,0, 0,0, 0);
}